// round 3
// baseline (speedup 1.0000x reference)
#include <cuda_runtime.h>
#include <cuda_bf16.h>
#include <math_constants.h>

#define BB 4
#define NN 2048
#define IND 256
#define OUTD 256
#define HH 4
#define HD 64

__device__ float g_Wh[BB * NN * OUTD];
__device__ float g_multi[BB * NN * OUTD];
__device__ float g_ssrc[BB * HH * NN];
__device__ float g_sdst[BB * HH * NN];
__device__ float g_Wcat[IND * OUTD];
__device__ float g_WoutT[OUTD * OUTD];

// ---------------- weight re-layout (writes globals directly) ----------------
__global__ void transpose_kernel(const float* __restrict__ W,
                                 const float* __restrict__ Wout) {
    int idx = blockIdx.x * 256 + threadIdx.x;   // < 65536
    int k = idx >> 8, c = idx & 255;
    int h = c >> 6, d = c & 63;
    g_Wcat[idx] = W[h * (IND * HD) + k * HD + d];
    g_WoutT[k * 256 + c] = Wout[c * 256 + k];
}

// ---------------- SGEMM core (device function) ----------------
__device__ __forceinline__ void sgemm_body(const float* __restrict__ A,
                                           const float* __restrict__ Bm,
                                           float* __restrict__ C,
                                           const float* __restrict__ bias,
                                           bool has_bias) {
    __shared__ float As[16][68];
    __shared__ float Bs[16][64];
    int t = threadIdx.x;
    int m0 = blockIdx.y * 64, n0 = blockIdx.x * 64;
    int ty = t >> 4, tx = t & 15;
    float acc[4][4] = {};

    int arow = t >> 2, akk = (t & 3) * 4;
    int bk = t >> 4, bcol = (t & 15) * 4;

    for (int k0 = 0; k0 < 256; k0 += 16) {
        float4 av = *(const float4*)&A[(m0 + arow) * 256 + k0 + akk];
        As[akk + 0][arow] = av.x;
        As[akk + 1][arow] = av.y;
        As[akk + 2][arow] = av.z;
        As[akk + 3][arow] = av.w;
        *(float4*)&Bs[bk][bcol] = *(const float4*)&Bm[(k0 + bk) * 256 + n0 + bcol];
        __syncthreads();
#pragma unroll
        for (int k = 0; k < 16; k++) {
            float4 a4 = *(const float4*)&As[k][ty * 4];
            float4 b4 = *(const float4*)&Bs[k][tx * 4];
            float aa[4] = {a4.x, a4.y, a4.z, a4.w};
            float bb[4] = {b4.x, b4.y, b4.z, b4.w};
#pragma unroll
            for (int i = 0; i < 4; i++)
#pragma unroll
                for (int j = 0; j < 4; j++)
                    acc[i][j] = fmaf(aa[i], bb[j], acc[i][j]);
        }
        __syncthreads();
    }
#pragma unroll
    for (int i = 0; i < 4; i++) {
        int row = m0 + ty * 4 + i;
        float4 o;
        o.x = acc[i][0]; o.y = acc[i][1]; o.z = acc[i][2]; o.w = acc[i][3];
        if (has_bias) {
            float4 bv = *(const float4*)&bias[n0 + tx * 4];
            o.x += bv.x; o.y += bv.y; o.z += bv.z; o.w += bv.w;
        }
        *(float4*)&C[row * 256 + n0 + tx * 4] = o;
    }
}

// Wh = x @ Wcat  (globals for Bm and C)
__global__ void __launch_bounds__(256) sgemm_wh(const float* __restrict__ x) {
    sgemm_body(x, g_Wcat, g_Wh, nullptr, false);
}
// out = multi @ WoutT + bout  (globals for A and Bm)
__global__ void __launch_bounds__(256) sgemm_out(float* __restrict__ out,
                                                 const float* __restrict__ bout) {
    sgemm_body(g_multi, g_WoutT, out, bout, true);
}

// ---------------- per-node attention logits ----------------
__global__ void s_kernel(const float* __restrict__ a) {
    int idx = blockIdx.x * 256 + threadIdx.x;   // < 32768
    int b = idx >> 13;
    int r = idx & 8191;
    int h = r >> 11;
    int n = r & 2047;
    const float4* row = (const float4*)(g_Wh + ((size_t)(b * NN + n)) * 256 + h * 64);
    float ss = 0.f, sd = 0.f;
#pragma unroll
    for (int q = 0; q < 16; q++) {
        float4 v = row[q];
        float4 as = ((const float4*)a)[q];
        float4 ad = ((const float4*)(a + 64))[q];
        ss += v.x * as.x + v.y * as.y + v.z * as.z + v.w * as.w;
        sd += v.x * ad.x + v.y * ad.y + v.z * ad.z + v.w * ad.w;
    }
    g_ssrc[idx] = ss;
    g_sdst[idx] = sd;
}

// ---------------- flash-style masked GAT attention ----------------
#define TI 64
#define TJ 32
__global__ void __launch_bounds__(512) attn_kernel(const int* __restrict__ adj) {
    __shared__ float WhS[TJ * 256];
    __shared__ int adjS[TI * 33];
    __shared__ float sjS[HH * TJ];

    int t = threadIdx.x;
    int b = blockIdx.y;
    int i0 = blockIdx.x * TI;
    int iA = t & 63;
    int hA = (t >> 6) & 3;
    int dg = t >> 8;
    int cbase = hA * 64 + dg * 32;

    float acc[32];
#pragma unroll
    for (int q = 0; q < 32; q++) acc[q] = 0.f;
    float m_run = -CUDART_INF_F;
    float l_run = 0.f;
    float si = g_ssrc[b * (HH * NN) + hA * NN + i0 + iA];

    const float* WhB = g_Wh + (size_t)b * NN * 256;
    const int* adjB = adj + ((size_t)(b * NN + i0)) * NN;

    for (int j0 = 0; j0 < NN; j0 += TJ) {
        {
            int row = t >> 3, c4 = (t & 7) << 2;
            int4 v = *(const int4*)&adjB[row * NN + j0 + c4];
            adjS[row * 33 + c4 + 0] = v.x;
            adjS[row * 33 + c4 + 1] = v.y;
            adjS[row * 33 + c4 + 2] = v.z;
            adjS[row * 33 + c4 + 3] = v.w;
        }
#pragma unroll
        for (int it = 0; it < 4; it++) {
            int idx = t + it * 512;
            int row = idx >> 6, c4 = (idx & 63) << 2;
            *(float4*)&WhS[row * 256 + c4] = *(const float4*)&WhB[(size_t)(j0 + row) * 256 + c4];
        }
        if (t < 128) sjS[t] = g_sdst[b * (HH * NN) + (t >> 5) * NN + j0 + (t & 31)];
        __syncthreads();

        float sv[TJ];
        float tmax = -CUDART_INF_F;
#pragma unroll
        for (int jj = 0; jj < TJ; jj++) {
            float s = si + sjS[hA * TJ + jj];
            s = s > 0.f ? s : 0.2f * s;
            if (adjS[iA * 33 + jj]) {
                sv[jj] = s;
                tmax = fmaxf(tmax, s);
            } else {
                sv[jj] = -CUDART_INF_F;
            }
        }
        float new_m = fmaxf(m_run, tmax);
        if (new_m != -CUDART_INF_F) {
            float scale = __expf(m_run - new_m);
            m_run = new_m;
            l_run *= scale;
#pragma unroll
            for (int q = 0; q < 32; q++) acc[q] *= scale;
#pragma unroll
            for (int jj = 0; jj < TJ; jj++) {
                float e = (sv[jj] == -CUDART_INF_F) ? 0.f : __expf(sv[jj] - new_m);
                l_run += e;
                const float* wrow = &WhS[jj * 256 + cbase];
#pragma unroll
                for (int q = 0; q < 8; q++) {
                    float4 w = *(const float4*)&wrow[q * 4];
                    acc[q * 4 + 0] = fmaf(e, w.x, acc[q * 4 + 0]);
                    acc[q * 4 + 1] = fmaf(e, w.y, acc[q * 4 + 1]);
                    acc[q * 4 + 2] = fmaf(e, w.z, acc[q * 4 + 2]);
                    acc[q * 4 + 3] = fmaf(e, w.w, acc[q * 4 + 3]);
                }
            }
        }
        __syncthreads();
    }

    float invl = 1.f / l_run;
    float* orow = g_multi + ((size_t)(b * NN + i0 + iA)) * 256 + cbase;
#pragma unroll
    for (int q = 0; q < 8; q++) {
        float4 o;
        o.x = acc[q * 4 + 0] * invl;
        o.y = acc[q * 4 + 1] * invl;
        o.z = acc[q * 4 + 2] * invl;
        o.w = acc[q * 4 + 3] * invl;
        *(float4*)&orow[q * 4] = o;
    }
}

// ---------------- launch: kernel launches ONLY ----------------
extern "C" void kernel_launch(void* const* d_in, const int* in_sizes, int n_in,
                              void* d_out, int out_size) {
    const float* x    = (const float*)d_in[0];
    const int*   adj  = (const int*)d_in[1];
    const float* W    = (const float*)d_in[2];
    const float* a    = (const float*)d_in[3];
    const float* Wout = (const float*)d_in[4];
    const float* bout = (const float*)d_in[5];
    float* out = (float*)d_out;

    transpose_kernel<<<256, 256>>>(W, Wout);
    sgemm_wh<<<dim3(4, 128), 256>>>(x);
    s_kernel<<<128, 256>>>(a);
    attn_kernel<<<dim3(NN / TI, BB), 512>>>(adj);
    sgemm_out<<<dim3(4, 128), 256>>>(out, bout);
}

// round 5
// speedup vs baseline: 1.0358x; 1.0358x over previous
#include <cuda_runtime.h>
#include <math_constants.h>

#define BB 4
#define NN 2048
#define IND 256
#define OUTD 256
#define HH 4
#define HD 64
#define TI 32
#define TJ 16

// ---------------- scratch ----------------
__device__ float g_Wh[BB * NN * OUTD];      // [b*N+n][h*64+d]
__device__ float g_multi[BB * NN * OUTD];
__device__ float g_ssrc[BB * HH * NN];      // raw s_src
__device__ float g_sdst[BB * HH * NN];      // raw s_dst
__device__ float g_esrP[BB * HH * NN];      // exp(s_src)
__device__ float g_esrN[BB * HH * NN];      // exp(0.2*s_src)
__device__ float g_esdP[BB * HH * NN];      // exp(s_dst)
__device__ float g_esdN[BB * HH * NN];      // exp(0.2*s_dst)
__device__ float g_Wcat[IND * OUTD];
__device__ float g_WoutT[OUTD * OUTD];

// ---------------- weight re-layout ----------------
__global__ void transpose_kernel(const float* __restrict__ W,
                                 const float* __restrict__ Wout) {
    int idx = blockIdx.x * 256 + threadIdx.x;   // < 65536
    int k = idx >> 8, c = idx & 255;
    int h = c >> 6, d = c & 63;
    g_Wcat[idx] = W[h * (IND * HD) + k * HD + d];
    g_WoutT[k * 256 + c] = Wout[c * 256 + k];
}

// ---------------- SGEMM core ----------------
__device__ __forceinline__ void sgemm_body(const float* __restrict__ A,
                                           const float* __restrict__ Bm,
                                           float* __restrict__ C,
                                           const float* __restrict__ bias,
                                           bool has_bias) {
    __shared__ float As[16][68];
    __shared__ float Bs[16][64];
    int t = threadIdx.x;
    int m0 = blockIdx.y * 64, n0 = blockIdx.x * 64;
    int ty = t >> 4, tx = t & 15;
    float acc[4][4] = {};
    int arow = t >> 2, akk = (t & 3) * 4;
    int bk = t >> 4, bcol = (t & 15) * 4;

    for (int k0 = 0; k0 < 256; k0 += 16) {
        float4 av = *(const float4*)&A[(m0 + arow) * 256 + k0 + akk];
        As[akk + 0][arow] = av.x;
        As[akk + 1][arow] = av.y;
        As[akk + 2][arow] = av.z;
        As[akk + 3][arow] = av.w;
        *(float4*)&Bs[bk][bcol] = *(const float4*)&Bm[(k0 + bk) * 256 + n0 + bcol];
        __syncthreads();
#pragma unroll
        for (int k = 0; k < 16; k++) {
            float4 a4 = *(const float4*)&As[k][ty * 4];
            float4 b4 = *(const float4*)&Bs[k][tx * 4];
            float aa[4] = {a4.x, a4.y, a4.z, a4.w};
            float bb[4] = {b4.x, b4.y, b4.z, b4.w};
#pragma unroll
            for (int i = 0; i < 4; i++)
#pragma unroll
                for (int j = 0; j < 4; j++)
                    acc[i][j] = fmaf(aa[i], bb[j], acc[i][j]);
        }
        __syncthreads();
    }
#pragma unroll
    for (int i = 0; i < 4; i++) {
        int row = m0 + ty * 4 + i;
        float4 o;
        o.x = acc[i][0]; o.y = acc[i][1]; o.z = acc[i][2]; o.w = acc[i][3];
        if (has_bias) {
            float4 bv = *(const float4*)&bias[n0 + tx * 4];
            o.x += bv.x; o.y += bv.y; o.z += bv.z; o.w += bv.w;
        }
        *(float4*)&C[row * 256 + n0 + tx * 4] = o;
    }
}

__global__ void __launch_bounds__(256) sgemm_wh(const float* __restrict__ x) {
    sgemm_body(x, g_Wcat, g_Wh, nullptr, false);
}
__global__ void __launch_bounds__(256) sgemm_out(float* __restrict__ out,
                                                 const float* __restrict__ bout) {
    sgemm_body(g_multi, g_WoutT, out, bout, true);
}

// ---------------- per-node logits + factorized exps ----------------
__global__ void s_kernel(const float* __restrict__ a) {
    int idx = blockIdx.x * 256 + threadIdx.x;   // < 32768
    int b = idx >> 13;
    int r = idx & 8191;
    int h = r >> 11;
    int n = r & 2047;
    const float4* row = (const float4*)(g_Wh + ((size_t)(b * NN + n)) * 256 + h * 64);
    float ss = 0.f, sd = 0.f;
#pragma unroll
    for (int q = 0; q < 16; q++) {
        float4 v = row[q];
        float4 as = ((const float4*)a)[q];
        float4 ad = ((const float4*)(a + 64))[q];
        ss += v.x * as.x + v.y * as.y + v.z * as.z + v.w * as.w;
        sd += v.x * ad.x + v.y * ad.y + v.z * ad.z + v.w * ad.w;
    }
    g_ssrc[idx] = ss;
    g_sdst[idx] = sd;
    g_esrP[idx] = __expf(ss);
    g_esrN[idx] = __expf(0.2f * ss);
    g_esdP[idx] = __expf(sd);
    g_esdN[idx] = __expf(0.2f * sd);
}

// ---------------- attention: exp-free scores + GEMM-style P·V ----------------
// CTA = 32 i-rows x 4 heads. 256 threads. grid (64, 4).
// Phase A thread: (iA = t&31, hA = (t>>5)&3, jh = t>>7) -> 8 e's/tile.
// Phase B thread: (hB = t>>6, tiB, tdB) -> 4i x 8d microtile per head.
__global__ void __launch_bounds__(256) attn_kernel(const int* __restrict__ adj) {
    __shared__ float WhS[TJ][256];        // 16 KB
    __shared__ float PS[HH][TJ][36];      // 9.2 KB (pad 36: float4-aligned, conflict-free)
    __shared__ int   adjS[TI][17];        // pad 17: column reads conflict-free
    __shared__ float sdS[HH][TJ], sjPS[HH][TJ], sjNS[HH][TJ];
    __shared__ float lS[HH][TI][2];

    int t = threadIdx.x;
    int b = blockIdx.y;
    int i0 = blockIdx.x * TI;

    // phase A identity
    int iA = t & 31;
    int hA = (t >> 5) & 3;
    int jh = t >> 7;                      // 0/1: which 8 j's
    int sbase = b * (HH * NN) + hA * NN + i0 + iA;
    float si   = g_ssrc[sbase];
    float esiP = g_esrP[sbase];
    float esiN = g_esrN[sbase];
    float le = 0.f;

    // phase B identity
    int rB = t & 63;
    int hB = t >> 6;
    int tiB = rB >> 3;                    // 0..7 : group of 4 i's
    int tdB = rB & 7;                     // 0..7 : group of 8 d's
    int dbase = hB * 64 + tdB * 8;
    float acc[4][8];
#pragma unroll
    for (int ii = 0; ii < 4; ii++)
#pragma unroll
        for (int dd = 0; dd < 8; dd++) acc[ii][dd] = 0.f;

    const float* WhB = g_Wh + (size_t)b * NN * 256;
    const int* adjB = adj + ((size_t)(b * NN + i0)) * NN;
    int sjbase = b * (HH * NN);

    for (int j0 = 0; j0 < NN; j0 += TJ) {
        // ---- stage Wh tile (16 x 256), adj tile (32 x 16), sj triples ----
#pragma unroll
        for (int it = 0; it < 4; it++) {
            int idx = t + it * 256;
            int row = idx >> 6, c4 = (idx & 63) << 2;
            *(float4*)&WhS[row][c4] = *(const float4*)&WhB[(size_t)(j0 + row) * 256 + c4];
        }
        if (t < 128) {
            int row = t >> 2, c0 = (t & 3) << 2;
            int4 v = *(const int4*)&adjB[row * NN + j0 + c0];
            adjS[row][c0 + 0] = v.x;
            adjS[row][c0 + 1] = v.y;
            adjS[row][c0 + 2] = v.z;
            adjS[row][c0 + 3] = v.w;
        } else {
            int u = t - 128;
            if (u < 64) {
                int hh = u >> 4, jj = u & 15;
                int off = sjbase + hh * NN + j0 + jj;
                sdS[hh][jj]  = g_sdst[off];
                sjPS[hh][jj] = g_esdP[off];
                sjNS[hh][jj] = g_esdN[off];
            }
        }
        __syncthreads();

        // ---- phase A: e = [adj] * (s>0 ? Ei*Ej : Ei2*Ej2), no exp, no max ----
#pragma unroll
        for (int k = 0; k < 8; k++) {
            int jj = jh * 8 + k;
            float sj = sdS[hA][jj];
            float e = (si + sj > 0.f) ? esiP * sjPS[hA][jj] : esiN * sjNS[hA][jj];
            e = adjS[iA][jj] ? e : 0.f;
            le += e;
            PS[hA][jj][iA] = e;
        }
        __syncthreads();

        // ---- phase B: out[32x64 per head] += P[32x16] x Wh[16x64] ----
#pragma unroll
        for (int jj = 0; jj < TJ; jj++) {
            float4 p  = *(const float4*)&PS[hB][jj][tiB * 4];
            float4 w0 = *(const float4*)&WhS[jj][dbase];
            float4 w1 = *(const float4*)&WhS[jj][dbase + 4];
            float pv[4] = {p.x, p.y, p.z, p.w};
            float wv[8] = {w0.x, w0.y, w0.z, w0.w, w1.x, w1.y, w1.z, w1.w};
#pragma unroll
            for (int ii = 0; ii < 4; ii++)
#pragma unroll
                for (int dd = 0; dd < 8; dd++)
                    acc[ii][dd] = fmaf(pv[ii], wv[dd], acc[ii][dd]);
        }
        __syncthreads();
    }

    // ---- l reduction + normalized output ----
    lS[hA][iA][jh] = le;
    __syncthreads();
#pragma unroll
    for (int ii = 0; ii < 4; ii++) {
        int i = tiB * 4 + ii;
        float l = lS[hB][i][0] + lS[hB][i][1];
        float invl = 1.f / l;
        float* orow = g_multi + ((size_t)(b * NN + i0 + i)) * 256 + dbase;
        float4 o0, o1;
        o0.x = acc[ii][0] * invl; o0.y = acc[ii][1] * invl;
        o0.z = acc[ii][2] * invl; o0.w = acc[ii][3] * invl;
        o1.x = acc[ii][4] * invl; o1.y = acc[ii][5] * invl;
        o1.z = acc[ii][6] * invl; o1.w = acc[ii][7] * invl;
        *(float4*)&orow[0] = o0;
        *(float4*)&orow[4] = o1;
    }
}

// ---------------- launch: kernel launches ONLY ----------------
extern "C" void kernel_launch(void* const* d_in, const int* in_sizes, int n_in,
                              void* d_out, int out_size) {
    const float* x    = (const float*)d_in[0];
    const int*   adj  = (const int*)d_in[1];
    const float* W    = (const float*)d_in[2];
    const float* a    = (const float*)d_in[3];
    const float* Wout = (const float*)d_in[4];
    const float* bout = (const float*)d_in[5];
    float* out = (float*)d_out;

    transpose_kernel<<<256, 256>>>(W, Wout);
    sgemm_wh<<<dim3(4, 128), 256>>>(x);
    s_kernel<<<128, 256>>>(a);
    attn_kernel<<<dim3(NN / TI, BB), 256>>>(adj);
    sgemm_out<<<dim3(4, 128), 256>>>(out, bout);
}

// round 6
// speedup vs baseline: 1.9598x; 1.8920x over previous
#include <cuda_runtime.h>
#include <math_constants.h>

#define BB 4
#define NN 2048
#define IND 256
#define OUTD 256
#define HH 4
#define HD 64
#define TI 32
#define TJ 32

// ---------------- scratch ----------------
__device__ float g_Wh[BB * NN * OUTD];      // [b*N+n][h*64+d]
__device__ float g_multi[BB * NN * OUTD];
__device__ float g_ssrc[BB * HH * NN];
__device__ float g_sdst[BB * HH * NN];
__device__ float g_esrP[BB * HH * NN];      // exp(s_src)
__device__ float g_esrN[BB * HH * NN];      // exp(0.2*s_src)
__device__ float g_esdP[BB * HH * NN];      // exp(s_dst)
__device__ float g_esdN[BB * HH * NN];      // exp(0.2*s_dst)
__device__ float g_Wcat[IND * OUTD];
__device__ float g_WoutT[OUTD * OUTD];

__device__ __forceinline__ unsigned tf32r(float x) {
    unsigned u;
    asm("cvt.rna.tf32.f32 %0, %1;" : "=r"(u) : "f"(x));
    return u;
}

// ---------------- weight re-layout ----------------
__global__ void transpose_kernel(const float* __restrict__ W,
                                 const float* __restrict__ Wout) {
    int idx = blockIdx.x * 256 + threadIdx.x;   // < 65536
    int k = idx >> 8, c = idx & 255;
    int h = c >> 6, d = c & 63;
    g_Wcat[idx] = W[h * (IND * HD) + k * HD + d];
    g_WoutT[k * 256 + c] = Wout[c * 256 + k];
}

// ---------------- SGEMM core (fp32, for projections) ----------------
__device__ __forceinline__ void sgemm_body(const float* __restrict__ A,
                                           const float* __restrict__ Bm,
                                           float* __restrict__ C,
                                           const float* __restrict__ bias,
                                           bool has_bias) {
    __shared__ float As[16][68];
    __shared__ float Bs[16][64];
    int t = threadIdx.x;
    int m0 = blockIdx.y * 64, n0 = blockIdx.x * 64;
    int ty = t >> 4, tx = t & 15;
    float acc[4][4] = {};
    int arow = t >> 2, akk = (t & 3) * 4;
    int bk = t >> 4, bcol = (t & 15) * 4;

    for (int k0 = 0; k0 < 256; k0 += 16) {
        float4 av = *(const float4*)&A[(m0 + arow) * 256 + k0 + akk];
        As[akk + 0][arow] = av.x;
        As[akk + 1][arow] = av.y;
        As[akk + 2][arow] = av.z;
        As[akk + 3][arow] = av.w;
        *(float4*)&Bs[bk][bcol] = *(const float4*)&Bm[(k0 + bk) * 256 + n0 + bcol];
        __syncthreads();
#pragma unroll
        for (int k = 0; k < 16; k++) {
            float4 a4 = *(const float4*)&As[k][ty * 4];
            float4 b4 = *(const float4*)&Bs[k][tx * 4];
            float aa[4] = {a4.x, a4.y, a4.z, a4.w};
            float bb[4] = {b4.x, b4.y, b4.z, b4.w};
#pragma unroll
            for (int i = 0; i < 4; i++)
#pragma unroll
                for (int j = 0; j < 4; j++)
                    acc[i][j] = fmaf(aa[i], bb[j], acc[i][j]);
        }
        __syncthreads();
    }
#pragma unroll
    for (int i = 0; i < 4; i++) {
        int row = m0 + ty * 4 + i;
        float4 o;
        o.x = acc[i][0]; o.y = acc[i][1]; o.z = acc[i][2]; o.w = acc[i][3];
        if (has_bias) {
            float4 bv = *(const float4*)&bias[n0 + tx * 4];
            o.x += bv.x; o.y += bv.y; o.z += bv.z; o.w += bv.w;
        }
        *(float4*)&C[row * 256 + n0 + tx * 4] = o;
    }
}

__global__ void __launch_bounds__(256) sgemm_wh(const float* __restrict__ x) {
    sgemm_body(x, g_Wcat, g_Wh, nullptr, false);
}
__global__ void __launch_bounds__(256) sgemm_out(float* __restrict__ out,
                                                 const float* __restrict__ bout) {
    sgemm_body(g_multi, g_WoutT, out, bout, true);
}

// ---------------- per-node logits + factorized exps ----------------
__global__ void s_kernel(const float* __restrict__ a) {
    int idx = blockIdx.x * 256 + threadIdx.x;   // < 32768
    int b = idx >> 13;
    int r = idx & 8191;
    int h = r >> 11;
    int n = r & 2047;
    const float4* row = (const float4*)(g_Wh + ((size_t)(b * NN + n)) * 256 + h * 64);
    float ss = 0.f, sd = 0.f;
#pragma unroll
    for (int q = 0; q < 16; q++) {
        float4 v = row[q];
        float4 as = ((const float4*)a)[q];
        float4 ad = ((const float4*)(a + 64))[q];
        ss += v.x * as.x + v.y * as.y + v.z * as.z + v.w * as.w;
        sd += v.x * ad.x + v.y * ad.y + v.z * ad.z + v.w * ad.w;
    }
    g_ssrc[idx] = ss;
    g_sdst[idx] = sd;
    g_esrP[idx] = __expf(ss);
    g_esrN[idx] = __expf(0.2f * ss);
    g_esdP[idx] = __expf(sd);
    g_esdN[idx] = __expf(0.2f * sd);
}

// ---------------- attention: tf32 mma.sync, P generated in fragments ----------------
// CTA: 128 threads = 4 warps. warp w: hl = w&1 (head within pair), is = w>>1 (16-row slice).
// grid: (NN/TI = 64, HH/2 = 2, BB = 4) = 512 CTAs.
// Each warp: D[16 x 64] = P[16 x 2048] x Wh[2048 x 64] via m16n8k8 tf32 mma,
// A-fragments (P) computed in registers from factorized exps; no P smem.
__global__ void __launch_bounds__(128) attn_kernel(const int* __restrict__ adj) {
    __shared__ float WhS[TJ][136];          // 2 heads x 64 cols, tf32-rounded; stride 136 -> conflict-free B loads
    __shared__ unsigned adjMask[TI];        // bitmask of tile's 32 j's per i-row
    __shared__ float sdS[2][TJ], edPS[2][TJ], edNS[2][TJ];

    int t = threadIdx.x;
    int lane = t & 31;
    int w = t >> 5;
    int hl = w & 1, is = w >> 1;
    int g = lane >> 2, c = lane & 3;

    int b = blockIdx.z;
    int h0 = blockIdx.y * 2;
    int i0 = blockIdx.x * TI;
    int h = h0 + hl;

    // per-thread i rows: iA = i0 + is*16 + g, iB = iA + 8
    int iA = i0 + is * 16 + g;
    int sbA = b * (HH * NN) + h * NN + iA;
    float siA = g_ssrc[sbA],     ePA = g_esrP[sbA],     eNA = g_esrN[sbA];
    float siB = g_ssrc[sbA + 8], ePB = g_esrP[sbA + 8], eNB = g_esrN[sbA + 8];

    float acc[8][4];
#pragma unroll
    for (int nt = 0; nt < 8; nt++)
#pragma unroll
        for (int q = 0; q < 4; q++) acc[nt][q] = 0.f;
    float leA = 0.f, leB = 0.f;

    const float* WhB = g_Wh + (size_t)b * NN * 256 + h0 * HD;   // this CTA's 128-col slice
    const int* adjB = adj + ((size_t)(b * NN + i0)) * NN;
    int sjb = b * (HH * NN);

    for (int j0 = 0; j0 < NN; j0 += TJ) {
        // ---- stage Wh tile: 32 rows x 128 cols, tf32-rounded ----
#pragma unroll
        for (int it = 0; it < 8; it++) {
            int f = t + it * 128;                 // 0..1023 float4 slots
            int row = f >> 5, c4 = (f & 31) << 2;
            float4 v = *(const float4*)&WhB[(size_t)(j0 + row) * 256 + c4];
            v.x = __uint_as_float(tf32r(v.x));
            v.y = __uint_as_float(tf32r(v.y));
            v.z = __uint_as_float(tf32r(v.z));
            v.w = __uint_as_float(tf32r(v.w));
            *(float4*)&WhS[row][c4] = v;
        }
        // ---- adj bitmasks: warp w covers rows w*8 .. w*8+7 ----
#pragma unroll
        for (int r8 = 0; r8 < 8; r8++) {
            int row = w * 8 + r8;
            int av = adjB[row * NN + j0 + lane];
            unsigned m = __ballot_sync(0xffffffffu, av != 0);
            if (lane == 0) adjMask[row] = m;
        }
        // ---- sd tables for both heads ----
        if (t < 64) {
            int hh = t >> 5, jj = t & 31;
            int off = sjb + (h0 + hh) * NN + j0 + jj;
            sdS[hh][jj]  = g_sdst[off];
            edPS[hh][jj] = g_esdP[off];
            edNS[hh][jj] = g_esdN[off];
        }
        __syncthreads();

        unsigned mA = adjMask[is * 16 + g];
        unsigned mB = adjMask[is * 16 + g + 8];

#pragma unroll
        for (int kc = 0; kc < 4; kc++) {
            int j1 = kc * 8 + c, j2 = j1 + 4;
            float sj1 = sdS[hl][j1], sj2 = sdS[hl][j2];
            float p1 = edPS[hl][j1], n1 = edNS[hl][j1];
            float p2 = edPS[hl][j2], n2 = edNS[hl][j2];
            float e0 = (siA + sj1 > 0.f) ? ePA * p1 : eNA * n1;   // (iA, j1)
            float e1 = (siB + sj1 > 0.f) ? ePB * p1 : eNB * n1;   // (iB, j1)
            float e2 = (siA + sj2 > 0.f) ? ePA * p2 : eNA * n2;   // (iA, j2)
            float e3 = (siB + sj2 > 0.f) ? ePB * p2 : eNB * n2;   // (iB, j2)
            e0 = ((mA >> j1) & 1u) ? e0 : 0.f;
            e1 = ((mB >> j1) & 1u) ? e1 : 0.f;
            e2 = ((mA >> j2) & 1u) ? e2 : 0.f;
            e3 = ((mB >> j2) & 1u) ? e3 : 0.f;
            leA += e0 + e2;
            leB += e1 + e3;
            unsigned a0 = tf32r(e0), a1 = tf32r(e1), a2 = tf32r(e2), a3 = tf32r(e3);
            const float* r1 = &WhS[j1][hl * 64 + g];
            const float* r2 = &WhS[j2][hl * 64 + g];
#pragma unroll
            for (int nt = 0; nt < 8; nt++) {
                unsigned b0 = __float_as_uint(r1[nt * 8]);
                unsigned b1 = __float_as_uint(r2[nt * 8]);
                asm volatile(
                    "mma.sync.aligned.m16n8k8.row.col.f32.tf32.tf32.f32 "
                    "{%0,%1,%2,%3}, {%4,%5,%6,%7}, {%8,%9}, {%0,%1,%2,%3};"
                    : "+f"(acc[nt][0]), "+f"(acc[nt][1]), "+f"(acc[nt][2]), "+f"(acc[nt][3])
                    : "r"(a0), "r"(a1), "r"(a2), "r"(a3), "r"(b0), "r"(b1));
            }
        }
        __syncthreads();
    }

    // ---- l reduction across the 4 c-lanes of each quad ----
    leA += __shfl_xor_sync(0xffffffffu, leA, 1);
    leA += __shfl_xor_sync(0xffffffffu, leA, 2);
    leB += __shfl_xor_sync(0xffffffffu, leB, 1);
    leB += __shfl_xor_sync(0xffffffffu, leB, 2);
    float invA = 1.f / leA, invB = 1.f / leB;

    // ---- epilogue: D rows g (c0,c1) and g+8 (c2,c3), cols nt*8 + 2c ----
    float* oA = g_multi + ((size_t)(b * NN + iA)) * 256 + h * HD;
    float* oB = oA + (size_t)8 * 256;
#pragma unroll
    for (int nt = 0; nt < 8; nt++) {
        float2 vA = {acc[nt][0] * invA, acc[nt][1] * invA};
        float2 vB = {acc[nt][2] * invB, acc[nt][3] * invB};
        *(float2*)&oA[nt * 8 + 2 * c] = vA;
        *(float2*)&oB[nt * 8 + 2 * c] = vB;
    }
}

// ---------------- launch: kernel launches ONLY ----------------
extern "C" void kernel_launch(void* const* d_in, const int* in_sizes, int n_in,
                              void* d_out, int out_size) {
    const float* x    = (const float*)d_in[0];
    const int*   adj  = (const int*)d_in[1];
    const float* W    = (const float*)d_in[2];
    const float* a    = (const float*)d_in[3];
    const float* Wout = (const float*)d_in[4];
    const float* bout = (const float*)d_in[5];
    float* out = (float*)d_out;

    transpose_kernel<<<256, 256>>>(W, Wout);
    sgemm_wh<<<dim3(4, 128), 256>>>(x);
    s_kernel<<<128, 256>>>(a);
    attn_kernel<<<dim3(NN / TI, HH / 2, BB), 128>>>(adj);
    sgemm_out<<<dim3(4, 128), 256>>>(out, bout);
}

// round 8
// speedup vs baseline: 2.8070x; 1.4323x over previous
#include <cuda_runtime.h>
#include <math_constants.h>

#define BB 4
#define NN 2048
#define IND 256
#define OUTD 256
#define HH 4
#define HD 64
#define TI 32
#define TJ 32

// ---------------- scratch ----------------
__device__ float g_Wh[BB * NN * OUTD];      // [b*N+n][h*64+d]
__device__ float g_multi[BB * NN * OUTD];
__device__ float g_ssrc[BB * HH * NN];
__device__ float g_esrP[BB * HH * NN];      // exp(s_src)
__device__ float g_esrN[BB * HH * NN];      // exp(0.2*s_src)
__device__ float4 g_pack[BB * HH * NN];     // (s_dst, exp(s_dst), exp(0.2 s_dst), 0)
__device__ float g_Wcat[IND * OUTD];
__device__ float g_WoutT[OUTD * OUTD];

__device__ __forceinline__ unsigned tf32r(float x) {
    unsigned u;
    asm("cvt.rna.tf32.f32 %0, %1;" : "=r"(u) : "f"(x));
    return u;
}
__device__ __forceinline__ void cpasync16(unsigned saddr, const void* g) {
    asm volatile("cp.async.cg.shared.global [%0], [%1], 16;" :: "r"(saddr), "l"(g));
}
__device__ __forceinline__ void cpcommit() {
    asm volatile("cp.async.commit_group;" ::: "memory");
}
__device__ __forceinline__ void cpwait1() {
    asm volatile("cp.async.wait_group 1;" ::: "memory");
}

// ---------------- weight re-layout ----------------
__global__ void transpose_kernel(const float* __restrict__ W,
                                 const float* __restrict__ Wout) {
    int idx = blockIdx.x * 256 + threadIdx.x;   // < 65536
    int k = idx >> 8, c = idx & 255;
    int h = c >> 6, d = c & 63;
    g_Wcat[idx] = W[h * (IND * HD) + k * HD + d];
    g_WoutT[k * 256 + c] = Wout[c * 256 + k];
}

// ---------------- SGEMM core (fp32, projections) ----------------
__device__ __forceinline__ void sgemm_body(const float* __restrict__ A,
                                           const float* __restrict__ Bm,
                                           float* __restrict__ C,
                                           const float* __restrict__ bias,
                                           bool has_bias) {
    __shared__ float As[16][68];
    __shared__ float Bs[16][64];
    int t = threadIdx.x;
    int m0 = blockIdx.y * 64, n0 = blockIdx.x * 64;
    int ty = t >> 4, tx = t & 15;
    float acc[4][4] = {};
    int arow = t >> 2, akk = (t & 3) * 4;
    int bk = t >> 4, bcol = (t & 15) * 4;

    for (int k0 = 0; k0 < 256; k0 += 16) {
        float4 av = *(const float4*)&A[(m0 + arow) * 256 + k0 + akk];
        As[akk + 0][arow] = av.x;
        As[akk + 1][arow] = av.y;
        As[akk + 2][arow] = av.z;
        As[akk + 3][arow] = av.w;
        *(float4*)&Bs[bk][bcol] = *(const float4*)&Bm[(k0 + bk) * 256 + n0 + bcol];
        __syncthreads();
#pragma unroll
        for (int k = 0; k < 16; k++) {
            float4 a4 = *(const float4*)&As[k][ty * 4];
            float4 b4 = *(const float4*)&Bs[k][tx * 4];
            float aa[4] = {a4.x, a4.y, a4.z, a4.w};
            float bb[4] = {b4.x, b4.y, b4.z, b4.w};
#pragma unroll
            for (int i = 0; i < 4; i++)
#pragma unroll
                for (int j = 0; j < 4; j++)
                    acc[i][j] = fmaf(aa[i], bb[j], acc[i][j]);
        }
        __syncthreads();
    }
#pragma unroll
    for (int i = 0; i < 4; i++) {
        int row = m0 + ty * 4 + i;
        float4 o;
        o.x = acc[i][0]; o.y = acc[i][1]; o.z = acc[i][2]; o.w = acc[i][3];
        if (has_bias) {
            float4 bv = *(const float4*)&bias[n0 + tx * 4];
            o.x += bv.x; o.y += bv.y; o.z += bv.z; o.w += bv.w;
        }
        *(float4*)&C[row * 256 + n0 + tx * 4] = o;
    }
}

__global__ void __launch_bounds__(256) sgemm_wh(const float* __restrict__ x) {
    sgemm_body(x, g_Wcat, g_Wh, nullptr, false);
}
__global__ void __launch_bounds__(256) sgemm_out(float* __restrict__ out,
                                                 const float* __restrict__ bout) {
    sgemm_body(g_multi, g_WoutT, out, bout, true);
}

// ---------------- per-node logits + factorized exps ----------------
__global__ void s_kernel(const float* __restrict__ a) {
    int idx = blockIdx.x * 256 + threadIdx.x;   // < 32768
    int b = idx >> 13;
    int r = idx & 8191;
    int h = r >> 11;
    int n = r & 2047;
    const float4* row = (const float4*)(g_Wh + ((size_t)(b * NN + n)) * 256 + h * 64);
    float ss = 0.f, sd = 0.f;
#pragma unroll
    for (int q = 0; q < 16; q++) {
        float4 v = row[q];
        float4 as = ((const float4*)a)[q];
        float4 ad = ((const float4*)(a + 64))[q];
        ss += v.x * as.x + v.y * as.y + v.z * as.z + v.w * as.w;
        sd += v.x * ad.x + v.y * ad.y + v.z * ad.z + v.w * ad.w;
    }
    g_ssrc[idx] = ss;
    g_esrP[idx] = __expf(ss);
    g_esrN[idx] = __expf(0.2f * ss);
    float4 pk;
    pk.x = sd;
    pk.y = __expf(sd);
    pk.z = __expf(0.2f * sd);
    pk.w = 0.f;
    g_pack[idx] = pk;
}

// ---------------- attention: tf32 mma + cp.async double-buffered tiles ----------------
// CTA: 128 threads = 4 warps. warp w: hl = w&1 (head in pair), is = w>>1 (16-row slice).
// grid: (NN/TI, HH/2, BB) = 512 CTAs.
__global__ void __launch_bounds__(128) attn_kernel(const int* __restrict__ adj) {
    __shared__ __align__(16) float  WhS[2][TJ][136];   // raw fp32 (mma truncates); stride 544B conflict-free
    __shared__ __align__(16) int    adjS[2][TJ][36];   // stride 144B; bank = 4g+c, conflict-free
    __shared__ float4 packS[2][2][TJ];                 // (sd, e+, e0.2) per head

    int t = threadIdx.x;
    int lane = t & 31;
    int w = t >> 5;
    int hl = w & 1, is = w >> 1;
    int g = lane >> 2, c = lane & 3;

    int b = blockIdx.z;
    int h0 = blockIdx.y * 2;
    int i0 = blockIdx.x * TI;
    int h = h0 + hl;

    int iA = i0 + is * 16 + g;
    int sbA = b * (HH * NN) + h * NN + iA;
    float siA = g_ssrc[sbA],     ePA = g_esrP[sbA],     eNA = g_esrN[sbA];
    float siB = g_ssrc[sbA + 8], ePB = g_esrP[sbA + 8], eNB = g_esrN[sbA + 8];

    float acc[8][4];
#pragma unroll
    for (int nt = 0; nt < 8; nt++)
#pragma unroll
        for (int q = 0; q < 4; q++) acc[nt][q] = 0.f;
    float leA = 0.f, leB = 0.f;

    const float* WhB = g_Wh + (size_t)b * NN * 256 + h0 * HD;
    const int* adjB = adj + ((size_t)(b * NN + i0)) * NN;
    const float4* packB = g_pack + b * (HH * NN);

    unsigned whsb  = (unsigned)__cvta_generic_to_shared(&WhS[0][0][0]);
    unsigned adjsb = (unsigned)__cvta_generic_to_shared(&adjS[0][0][0]);
    unsigned pksb  = (unsigned)__cvta_generic_to_shared(&packS[0][0][0]);
    const unsigned WHSZ = TJ * 136 * 4, ADSZ = TJ * 36 * 4, PKSZ = 2 * TJ * 16;

    int isg = is * 16 + g;

    // ---- stage tile j0 into buffer s ----
    auto stage = [&](int j0, int s) {
        unsigned wb = whsb + s * WHSZ;
#pragma unroll
        for (int k = 0; k < 8; k++) {
            int id = t + k * 128;                 // 1024 chunks of 16B
            int row = id >> 5, seg = id & 31;
            cpasync16(wb + row * 544 + seg * 16,
                      WhB + (size_t)(j0 + row) * 256 + seg * 4);
        }
        unsigned ab = adjsb + s * ADSZ;
#pragma unroll
        for (int k = 0; k < 2; k++) {
            int id = t + k * 128;                 // 256 chunks
            int row = id >> 3, seg = id & 7;
            cpasync16(ab + row * 144 + seg * 16,
                      adjB + (size_t)row * NN + j0 + seg * 4);
        }
        if (t < 64) {
            int hh = t >> 5, jj = t & 31;
            cpasync16(pksb + s * PKSZ + t * 16,
                      packB + (h0 + hh) * NN + j0 + jj);
        }
    };

    stage(0, 0);
    cpcommit();

    for (int tile = 0; tile < NN / TJ; tile++) {
        int s = tile & 1;
        if (tile + 1 < NN / TJ) stage((tile + 1) * TJ, s ^ 1);
        cpcommit();
        cpwait1();
        __syncthreads();

#pragma unroll
        for (int kc = 0; kc < 4; kc++) {
            int j1 = kc * 8 + c, j2 = j1 + 4;
            float4 P1 = packS[s][hl][j1];
            float4 P2 = packS[s][hl][j2];
            int aA1 = adjS[s][isg][j1],     aA2 = adjS[s][isg][j2];
            int aB1 = adjS[s][isg + 8][j1], aB2 = adjS[s][isg + 8][j2];
            float e0 = (siA + P1.x > 0.f) ? ePA * P1.y : eNA * P1.z;
            float e1 = (siB + P1.x > 0.f) ? ePB * P1.y : eNB * P1.z;
            float e2 = (siA + P2.x > 0.f) ? ePA * P2.y : eNA * P2.z;
            float e3 = (siB + P2.x > 0.f) ? ePB * P2.y : eNB * P2.z;
            e0 = aA1 ? e0 : 0.f;
            e1 = aB1 ? e1 : 0.f;
            e2 = aA2 ? e2 : 0.f;
            e3 = aB2 ? e3 : 0.f;
            leA += e0 + e2;
            leB += e1 + e3;
            unsigned a0 = tf32r(e0), a1 = tf32r(e1), a2 = tf32r(e2), a3 = tf32r(e3);
            const float* r1 = &WhS[s][j1][hl * 64 + g];
            const float* r2 = &WhS[s][j2][hl * 64 + g];
#pragma unroll
            for (int nt = 0; nt < 8; nt++) {
                unsigned b0 = __float_as_uint(r1[nt * 8]);
                unsigned b1 = __float_as_uint(r2[nt * 8]);
                asm volatile(
                    "mma.sync.aligned.m16n8k8.row.col.f32.tf32.tf32.f32 "
                    "{%0,%1,%2,%3}, {%4,%5,%6,%7}, {%8,%9}, {%0,%1,%2,%3};"
                    : "+f"(acc[nt][0]), "+f"(acc[nt][1]), "+f"(acc[nt][2]), "+f"(acc[nt][3])
                    : "r"(a0), "r"(a1), "r"(a2), "r"(a3), "r"(b0), "r"(b1));
            }
        }
        __syncthreads();
    }

    // ---- l reduction across the 4 c-lanes of each quad ----
    leA += __shfl_xor_sync(0xffffffffu, leA, 1);
    leA += __shfl_xor_sync(0xffffffffu, leA, 2);
    leB += __shfl_xor_sync(0xffffffffu, leB, 1);
    leB += __shfl_xor_sync(0xffffffffu, leB, 2);
    float invA = 1.f / leA, invB = 1.f / leB;

    float* oA = g_multi + ((size_t)(b * NN + iA)) * 256 + h * HD;
    float* oB = oA + (size_t)8 * 256;
#pragma unroll
    for (int nt = 0; nt < 8; nt++) {
        float2 vA = {acc[nt][0] * invA, acc[nt][1] * invA};
        float2 vB = {acc[nt][2] * invB, acc[nt][3] * invB};
        *(float2*)&oA[nt * 8 + 2 * c] = vA;
        *(float2*)&oB[nt * 8 + 2 * c] = vB;
    }
}

// ---------------- launch: kernel launches ONLY ----------------
extern "C" void kernel_launch(void* const* d_in, const int* in_sizes, int n_in,
                              void* d_out, int out_size) {
    const float* x    = (const float*)d_in[0];
    const int*   adj  = (const int*)d_in[1];
    const float* W    = (const float*)d_in[2];
    const float* a    = (const float*)d_in[3];
    const float* Wout = (const float*)d_in[4];
    const float* bout = (const float*)d_in[5];
    float* out = (float*)d_out;

    transpose_kernel<<<256, 256>>>(W, Wout);
    sgemm_wh<<<dim3(4, 128), 256>>>(x);
    s_kernel<<<128, 256>>>(a);
    attn_kernel<<<dim3(NN / TI, HH / 2, BB), 128>>>(adj);
    sgemm_out<<<dim3(4, 128), 256>>>(out, bout);
}

// round 9
// speedup vs baseline: 3.1451x; 1.1205x over previous
#include <cuda_runtime.h>
#include <math_constants.h>

#define BB 4
#define NN 2048
#define IND 256
#define OUTD 256
#define HH 4
#define HD 64
#define TI 32
#define TJ 32

// ---------------- scratch ----------------
__device__ float g_Wh[BB * NN * OUTD];      // [b*N+n][h*64+d]
__device__ float g_multi[BB * NN * OUTD];
__device__ float g_ssrc[BB * HH * NN];
__device__ float g_esrP[BB * HH * NN];      // exp(s_src)
__device__ float g_esrN[BB * HH * NN];      // exp(0.2*s_src)
__device__ float4 g_pack[BB * HH * NN];     // (s_dst, exp(s_dst), exp(0.2 s_dst), 0)
__device__ float g_WcatH[IND * OUTD];       // tf32-rounded hi
__device__ float g_WcatL[IND * OUTD];       // tf32 residual lo
__device__ float g_WoutTH[OUTD * OUTD];
__device__ float g_WoutTL[OUTD * OUTD];

__device__ __forceinline__ unsigned tf32r(float x) {
    unsigned u;
    asm("cvt.rna.tf32.f32 %0, %1;" : "=r"(u) : "f"(x));
    return u;
}
__device__ __forceinline__ void cpasync16(unsigned saddr, const void* g) {
    asm volatile("cp.async.cg.shared.global [%0], [%1], 16;" :: "r"(saddr), "l"(g));
}
__device__ __forceinline__ void cpcommit() {
    asm volatile("cp.async.commit_group;" ::: "memory");
}
__device__ __forceinline__ void cpwait1() {
    asm volatile("cp.async.wait_group 1;" ::: "memory");
}
#define MMA_TF32(accv, af, b0, b1)                                              \
    asm volatile(                                                               \
        "mma.sync.aligned.m16n8k8.row.col.f32.tf32.tf32.f32 "                   \
        "{%0,%1,%2,%3}, {%4,%5,%6,%7}, {%8,%9}, {%0,%1,%2,%3};"                 \
        : "+f"(accv[0]), "+f"(accv[1]), "+f"(accv[2]), "+f"(accv[3])            \
        : "r"(af[0]), "r"(af[1]), "r"(af[2]), "r"(af[3]), "r"(b0), "r"(b1))

// ---------------- weight re-layout + tf32 hi/lo split ----------------
__global__ void transpose_kernel(const float* __restrict__ W,
                                 const float* __restrict__ Wout) {
    int idx = blockIdx.x * 256 + threadIdx.x;   // < 65536
    int k = idx >> 8, cc = idx & 255;
    int h = cc >> 6, d = cc & 63;
    float wv = W[h * (IND * HD) + k * HD + d];
    unsigned wh = tf32r(wv);
    g_WcatH[idx] = __uint_as_float(wh);
    g_WcatL[idx] = __uint_as_float(tf32r(wv - __uint_as_float(wh)));
    float ov = Wout[cc * 256 + k];
    unsigned oh = tf32r(ov);
    g_WoutTH[k * 256 + cc] = __uint_as_float(oh);
    g_WoutTL[k * 256 + cc] = __uint_as_float(tf32r(ov - __uint_as_float(oh)));
}

// ---------------- tf32x3 MMA GEMM: C[Mx256] = A[Mx256] @ B[256x256] (+bias) ----------------
// CTA tile 128x64, 256 thr = 8 warps (4 m x 2 n), warp tile 32x32.
// K staged 16/iter, double-buffered cp.async. B hi/lo precomputed in global.
__device__ __forceinline__ void mma_gemm_body(const float* __restrict__ A,
                                              const float* __restrict__ BH,
                                              const float* __restrict__ BL,
                                              float* __restrict__ C,
                                              const float* __restrict__ bias,
                                              bool has_bias) {
    __shared__ __align__(16) float As[2][128][20];   // row stride 80B, frag bank = 20g+c (distinct)
    __shared__ __align__(16) float BsH[2][16][68];   // row stride 272B, frag bank = 4c+g (distinct)
    __shared__ __align__(16) float BsL[2][16][68];

    int t = threadIdx.x, lane = t & 31, w = t >> 5;
    int g = lane >> 2, c = lane & 3;
    int mw = w & 3, nw = w >> 2;
    int m0 = blockIdx.y * 128, n0 = blockIdx.x * 64;
    int mb = mw * 32, nb = nw * 32;

    unsigned asb = (unsigned)__cvta_generic_to_shared(&As[0][0][0]);
    unsigned bhb = (unsigned)__cvta_generic_to_shared(&BsH[0][0][0]);
    unsigned blb = (unsigned)__cvta_generic_to_shared(&BsL[0][0][0]);

    auto stage = [&](int k0, int buf) {
#pragma unroll
        for (int q = 0; q < 2; q++) {
            int id = t + q * 256;                    // 512 chunks: 128 rows x 4
            int row = id >> 2, seg = id & 3;
            cpasync16(asb + buf * 10240 + row * 80 + seg * 16,
                      A + (size_t)(m0 + row) * 256 + k0 + seg * 4);
        }
        int row = t >> 4, seg = t & 15;              // 256 chunks: 16 rows x 16
        cpasync16(bhb + buf * 4352 + row * 272 + seg * 16,
                  BH + (size_t)(k0 + row) * 256 + n0 + seg * 4);
        cpasync16(blb + buf * 4352 + row * 272 + seg * 16,
                  BL + (size_t)(k0 + row) * 256 + n0 + seg * 4);
    };

    float acc[2][4][4] = {};

    stage(0, 0);
    cpcommit();
    for (int s = 0; s < 16; s++) {
        int buf = s & 1;
        if (s < 15) stage((s + 1) * 16, buf ^ 1);
        cpcommit();
        cpwait1();
        __syncthreads();
#pragma unroll
        for (int kk = 0; kk < 16; kk += 8) {
            unsigned ah[2][4], al[2][4];
#pragma unroll
            for (int mi = 0; mi < 2; mi++) {
                int r0 = mb + mi * 16 + g;
#pragma unroll
                for (int q = 0; q < 4; q++) {
                    int rr = r0 + (q & 1) * 8;
                    int ck = kk + c + (q >> 1) * 4;
                    float v = As[buf][rr][ck];
                    unsigned hb = tf32r(v);
                    ah[mi][q] = hb;
                    al[mi][q] = tf32r(v - __uint_as_float(hb));
                }
            }
#pragma unroll
            for (int ni = 0; ni < 4; ni++) {
                int col = nb + ni * 8 + g;
                unsigned bh0 = __float_as_uint(BsH[buf][kk + c][col]);
                unsigned bh1 = __float_as_uint(BsH[buf][kk + c + 4][col]);
                unsigned bl0 = __float_as_uint(BsL[buf][kk + c][col]);
                unsigned bl1 = __float_as_uint(BsL[buf][kk + c + 4][col]);
#pragma unroll
                for (int mi = 0; mi < 2; mi++) {
                    MMA_TF32(acc[mi][ni], al[mi], bh0, bh1);   // lo*hi correction
                    MMA_TF32(acc[mi][ni], ah[mi], bl0, bl1);   // hi*lo correction
                    MMA_TF32(acc[mi][ni], ah[mi], bh0, bh1);   // main
                }
            }
        }
        __syncthreads();
    }

#pragma unroll
    for (int mi = 0; mi < 2; mi++) {
#pragma unroll
        for (int ni = 0; ni < 4; ni++) {
            int col = n0 + nb + ni * 8 + 2 * c;
            float bx = 0.f, by = 0.f;
            if (has_bias) {
                float2 bv = *(const float2*)&bias[col];
                bx = bv.x; by = bv.y;
            }
            int r0 = m0 + mb + mi * 16 + g;
            float2 v0 = {acc[mi][ni][0] + bx, acc[mi][ni][1] + by};
            float2 v1 = {acc[mi][ni][2] + bx, acc[mi][ni][3] + by};
            *(float2*)&C[(size_t)r0 * 256 + col] = v0;
            *(float2*)&C[(size_t)(r0 + 8) * 256 + col] = v1;
        }
    }
}

__global__ void __launch_bounds__(256) gemm_wh(const float* __restrict__ x) {
    mma_gemm_body(x, g_WcatH, g_WcatL, g_Wh, nullptr, false);
}
__global__ void __launch_bounds__(256) gemm_out(float* __restrict__ out,
                                                const float* __restrict__ bout) {
    mma_gemm_body(g_multi, g_WoutTH, g_WoutTL, out, bout, true);
}

// ---------------- per-node logits + factorized exps ----------------
__global__ void s_kernel(const float* __restrict__ a) {
    int idx = blockIdx.x * 256 + threadIdx.x;   // < 32768
    int b = idx >> 13;
    int r = idx & 8191;
    int h = r >> 11;
    int n = r & 2047;
    const float4* row = (const float4*)(g_Wh + ((size_t)(b * NN + n)) * 256 + h * 64);
    float ss = 0.f, sd = 0.f;
#pragma unroll
    for (int q = 0; q < 16; q++) {
        float4 v = row[q];
        float4 as = ((const float4*)a)[q];
        float4 ad = ((const float4*)(a + 64))[q];
        ss += v.x * as.x + v.y * as.y + v.z * as.z + v.w * as.w;
        sd += v.x * ad.x + v.y * ad.y + v.z * ad.z + v.w * ad.w;
    }
    g_ssrc[idx] = ss;
    g_esrP[idx] = __expf(ss);
    g_esrN[idx] = __expf(0.2f * ss);
    float4 pk;
    pk.x = sd;
    pk.y = __expf(sd);
    pk.z = __expf(0.2f * sd);
    pk.w = 0.f;
    g_pack[idx] = pk;
}

// ---------------- attention: tf32 mma + cp.async double-buffered tiles ----------------
// (unchanged from round 8 — bench-verified at 108.8 us)
__global__ void __launch_bounds__(128) attn_kernel(const int* __restrict__ adj) {
    __shared__ __align__(16) float  WhS[2][TJ][136];
    __shared__ __align__(16) int    adjS[2][TJ][36];
    __shared__ float4 packS[2][2][TJ];

    int t = threadIdx.x;
    int lane = t & 31;
    int w = t >> 5;
    int hl = w & 1, is = w >> 1;
    int g = lane >> 2, c = lane & 3;

    int b = blockIdx.z;
    int h0 = blockIdx.y * 2;
    int i0 = blockIdx.x * TI;
    int h = h0 + hl;

    int iA = i0 + is * 16 + g;
    int sbA = b * (HH * NN) + h * NN + iA;
    float siA = g_ssrc[sbA],     ePA = g_esrP[sbA],     eNA = g_esrN[sbA];
    float siB = g_ssrc[sbA + 8], ePB = g_esrP[sbA + 8], eNB = g_esrN[sbA + 8];

    float acc[8][4];
#pragma unroll
    for (int nt = 0; nt < 8; nt++)
#pragma unroll
        for (int q = 0; q < 4; q++) acc[nt][q] = 0.f;
    float leA = 0.f, leB = 0.f;

    const float* WhB = g_Wh + (size_t)b * NN * 256 + h0 * HD;
    const int* adjB = adj + ((size_t)(b * NN + i0)) * NN;
    const float4* packB = g_pack + b * (HH * NN);

    unsigned whsb  = (unsigned)__cvta_generic_to_shared(&WhS[0][0][0]);
    unsigned adjsb = (unsigned)__cvta_generic_to_shared(&adjS[0][0][0]);
    unsigned pksb  = (unsigned)__cvta_generic_to_shared(&packS[0][0][0]);
    const unsigned WHSZ = TJ * 136 * 4, ADSZ = TJ * 36 * 4, PKSZ = 2 * TJ * 16;

    int isg = is * 16 + g;

    auto stage = [&](int j0, int s) {
        unsigned wb = whsb + s * WHSZ;
#pragma unroll
        for (int k = 0; k < 8; k++) {
            int id = t + k * 128;
            int row = id >> 5, seg = id & 31;
            cpasync16(wb + row * 544 + seg * 16,
                      WhB + (size_t)(j0 + row) * 256 + seg * 4);
        }
        unsigned ab = adjsb + s * ADSZ;
#pragma unroll
        for (int k = 0; k < 2; k++) {
            int id = t + k * 128;
            int row = id >> 3, seg = id & 7;
            cpasync16(ab + row * 144 + seg * 16,
                      adjB + (size_t)row * NN + j0 + seg * 4);
        }
        if (t < 64) {
            int hh = t >> 5, jj = t & 31;
            cpasync16(pksb + s * PKSZ + t * 16,
                      packB + (h0 + hh) * NN + j0 + jj);
        }
    };

    stage(0, 0);
    cpcommit();

    for (int tile = 0; tile < NN / TJ; tile++) {
        int s = tile & 1;
        if (tile + 1 < NN / TJ) stage((tile + 1) * TJ, s ^ 1);
        cpcommit();
        cpwait1();
        __syncthreads();

#pragma unroll
        for (int kc = 0; kc < 4; kc++) {
            int j1 = kc * 8 + c, j2 = j1 + 4;
            float4 P1 = packS[s][hl][j1];
            float4 P2 = packS[s][hl][j2];
            int aA1 = adjS[s][isg][j1],     aA2 = adjS[s][isg][j2];
            int aB1 = adjS[s][isg + 8][j1], aB2 = adjS[s][isg + 8][j2];
            float e0 = (siA + P1.x > 0.f) ? ePA * P1.y : eNA * P1.z;
            float e1 = (siB + P1.x > 0.f) ? ePB * P1.y : eNB * P1.z;
            float e2 = (siA + P2.x > 0.f) ? ePA * P2.y : eNA * P2.z;
            float e3 = (siB + P2.x > 0.f) ? ePB * P2.y : eNB * P2.z;
            e0 = aA1 ? e0 : 0.f;
            e1 = aB1 ? e1 : 0.f;
            e2 = aA2 ? e2 : 0.f;
            e3 = aB2 ? e3 : 0.f;
            leA += e0 + e2;
            leB += e1 + e3;
            unsigned a0 = tf32r(e0), a1 = tf32r(e1), a2 = tf32r(e2), a3 = tf32r(e3);
            const float* r1 = &WhS[s][j1][hl * 64 + g];
            const float* r2 = &WhS[s][j2][hl * 64 + g];
#pragma unroll
            for (int nt = 0; nt < 8; nt++) {
                unsigned b0 = __float_as_uint(r1[nt * 8]);
                unsigned b1 = __float_as_uint(r2[nt * 8]);
                asm volatile(
                    "mma.sync.aligned.m16n8k8.row.col.f32.tf32.tf32.f32 "
                    "{%0,%1,%2,%3}, {%4,%5,%6,%7}, {%8,%9}, {%0,%1,%2,%3};"
                    : "+f"(acc[nt][0]), "+f"(acc[nt][1]), "+f"(acc[nt][2]), "+f"(acc[nt][3])
                    : "r"(a0), "r"(a1), "r"(a2), "r"(a3), "r"(b0), "r"(b1));
            }
        }
        __syncthreads();
    }

    leA += __shfl_xor_sync(0xffffffffu, leA, 1);
    leA += __shfl_xor_sync(0xffffffffu, leA, 2);
    leB += __shfl_xor_sync(0xffffffffu, leB, 1);
    leB += __shfl_xor_sync(0xffffffffu, leB, 2);
    float invA = 1.f / leA, invB = 1.f / leB;

    float* oA = g_multi + ((size_t)(b * NN + iA)) * 256 + h * HD;
    float* oB = oA + (size_t)8 * 256;
#pragma unroll
    for (int nt = 0; nt < 8; nt++) {
        float2 vA = {acc[nt][0] * invA, acc[nt][1] * invA};
        float2 vB = {acc[nt][2] * invB, acc[nt][3] * invB};
        *(float2*)&oA[nt * 8 + 2 * c] = vA;
        *(float2*)&oB[nt * 8 + 2 * c] = vB;
    }
}

// ---------------- launch: kernel launches ONLY ----------------
extern "C" void kernel_launch(void* const* d_in, const int* in_sizes, int n_in,
                              void* d_out, int out_size) {
    const float* x    = (const float*)d_in[0];
    const int*   adj  = (const int*)d_in[1];
    const float* W    = (const float*)d_in[2];
    const float* a    = (const float*)d_in[3];
    const float* Wout = (const float*)d_in[4];
    const float* bout = (const float*)d_in[5];
    float* out = (float*)d_out;

    transpose_kernel<<<256, 256>>>(W, Wout);
    gemm_wh<<<dim3(4, 64), 256>>>(x);
    s_kernel<<<128, 256>>>(a);
    attn_kernel<<<dim3(NN / TI, HH / 2, BB), 128>>>(adj);
    gemm_out<<<dim3(4, 64), 256>>>(out, bout);
}